// round 15
// baseline (speedup 1.0000x reference)
#include <cuda_runtime.h>

#define IW 512
#define H 256
#define OW 512
#define E 64
#define NA 2048
#define NAP 2560
#define XP 2560           // column stride of g_vd
#define CH 32             // token chunk per worklist entry
#define MAXWL 128

typedef unsigned long long u64;

// ---------------- device scratch (no allocs allowed) ----------------
__device__ __align__(16) u64   g_vd[(size_t)H * XP];   // 5.2 MB (relu v, relu v) dup [h][perm]
__device__ int   g_topk_idx[NA];
__device__ float g_topk_score[NA];
__device__ int   g_seg_start[E + 1];
__device__ int   g_seg_cnt[E];
__device__ int   g_perm_a[NAP];
__device__ float g_perm_score[NAP];
__device__ int   g_wl[MAXWL];      // (expert<<16) | chunk_start
__device__ int   g_wl_n;

// ---------------- packed f32x2 helpers (sm_103a) ----------------
__device__ __forceinline__ u64 pack2(float a, float b) {
    u64 r; unsigned ai = __float_as_uint(a), bi = __float_as_uint(b);
    asm("mov.b64 %0, {%1, %2};" : "=l"(r) : "r"(ai), "r"(bi));
    return r;
}
__device__ __forceinline__ void ffma2(u64 &d, u64 a, u64 b) {
    asm("fma.rn.f32x2 %0, %1, %2, %0;" : "+l"(d) : "l"(a), "l"(b));
}
__device__ __forceinline__ float2 unpack2(u64 v) {
    unsigned lo, hi;
    asm("mov.b64 {%0, %1}, %2;" : "=r"(lo), "=r"(hi) : "l"(v));
    float2 f; f.x = __uint_as_float(lo); f.y = __uint_as_float(hi);
    return f;
}

// ---------------- kernel 1: routing (+ fused d_out zeroing) ----------------
__global__ __launch_bounds__(256) void routing_kernel(
    const float* __restrict__ x, const float* __restrict__ noise,
    const float* __restrict__ mixer, const float* __restrict__ nctl,
    float4* __restrict__ out)
{
    __shared__ __align__(16) u64 mns[32][64];
    __shared__ __align__(16) u64 xs2[8][32];
    __shared__ float hs[8][64];
    int tid = threadIdx.x;
    int t0 = blockIdx.x * 8;
    int ee = tid & 63, tg = tid >> 6;

    {   // fused zero of d_out: 131072 float4 over 32768 threads
        int base = blockIdx.x * 256 + tid;
        float4 z = make_float4(0.f, 0.f, 0.f, 0.f);
#pragma unroll
        for (int q = 0; q < 4; q++) out[base + q * 32768] = z;
    }

    u64 acc2[2] = {0ull, 0ull};

    for (int i0 = 0; i0 < IW; i0 += 32) {
#pragma unroll
        for (int q = 0; q < 8; q++) {
            int id = tid + 256 * q; int ii = id >> 6, e2 = id & 63;
            mns[ii][e2] = pack2(mixer[(i0 + ii) * E + e2], nctl[(i0 + ii) * E + e2]);
        }
        {
            int tt = tid >> 5, ii = tid & 31;
            if (tt < 8) {
                float v = x[(t0 + tt) * IW + i0 + ii];
                xs2[tt][ii] = pack2(v, v);
            }
        }
        __syncthreads();
#pragma unroll 8
        for (int ii = 0; ii < 32; ii++) {
            u64 mn = mns[ii][ee];
            ffma2(acc2[0], xs2[tg * 2 + 0][ii], mn);
            ffma2(acc2[1], xs2[tg * 2 + 1][ii], mn);
        }
        __syncthreads();
    }

#pragma unroll
    for (int j = 0; j < 2; j++) {
        int t = tg * 2 + j;
        float2 a = unpack2(acc2[j]);
        float z = a.y;
        float sp = (z > 20.f) ? z : log1pf(expf(z));
        hs[t][ee] = a.x + noise[(t0 + t) * E + ee] * sp;
    }
    __syncthreads();

    if (tid < 8) {
        int t = tid;
        float v0 = -1e30f, v1 = -1e30f; int i0 = -1, i1 = -1;
        for (int ec = 0; ec < 64; ec++) {
            float v = hs[t][ec];
            if (v > v0)      { v1 = v0; i1 = i0; v0 = v; i0 = ec; }
            else if (v > v1) { v1 = v; i1 = ec; }
        }
        float e1 = expf(v1 - v0);
        float s0 = 1.f / (1.f + e1);
        float s1 = e1 * s0;
        g_topk_idx[(t0 + t) * 2 + 0] = i0;
        g_topk_idx[(t0 + t) * 2 + 1] = i1;
        g_topk_score[(t0 + t) * 2 + 0] = s0;
        g_topk_score[(t0 + t) * 2 + 1] = s1;
    }
}

// ---------------- kernel 2: group + deterministic worklist ----------------
__global__ __launch_bounds__(256) void group_kernel()
{
    __shared__ int cnt4[4][E];
    __shared__ int st[E + 1];
    __shared__ int cur[E];
    __shared__ int wo[E];
    int tid = threadIdx.x;
    int grp = tid >> 6;
#pragma unroll
    for (int q = 0; q < E / 64; q++) { }
    if (tid < E) { cnt4[0][tid] = 0; cnt4[1][tid] = 0; cnt4[2][tid] = 0; cnt4[3][tid] = 0; }
    __syncthreads();
    for (int a = tid; a < NA; a += 256) atomicAdd(&cnt4[grp][g_topk_idx[a]], 1);
    __syncthreads();
    if (tid < E) cnt4[0][tid] += cnt4[1][tid] + cnt4[2][tid] + cnt4[3][tid];
    __syncthreads();
    if (tid == 0) {
        int run = 0, wrun = 0;
        for (int e2 = 0; e2 < E; e2++) {
            st[e2] = run;
            run = (run + cnt4[0][e2] + 7) & ~7;  // 8-aligned segment starts
            wo[e2] = wrun;
            wrun += (cnt4[0][e2] + CH - 1) / CH;
        }
        st[E] = run;
        g_wl_n = wrun;
    }
    __syncthreads();
    if (tid < E) { cur[tid] = st[tid]; g_seg_cnt[tid] = cnt4[0][tid]; }
    if (tid <= E) g_seg_start[tid] = st[tid];
    __syncthreads();
    for (int a = tid; a < NA; a += 256) {
        int e2 = g_topk_idx[a];
        int pos = atomicAdd(&cur[e2], 1);
        g_perm_a[pos] = a;
        g_perm_score[pos] = g_topk_score[a];
    }
    __syncthreads();
    if (tid < E) {
        for (int p = st[tid] + cnt4[0][tid]; p < st[tid + 1]; p++) {
            g_perm_a[p] = 0; g_perm_score[p] = 0.f;
        }
        for (int c = 0; c * CH < cnt4[0][tid]; c++)
            g_wl[wo[tid] + c] = (tid << 16) | (c * CH);
    }
    for (int p = st[E] + tid; p < NAP; p += 256) {
        g_perm_a[p] = 0; g_perm_score[p] = 0.f;
    }
}

// ---------------- kernel 3: ffn1 -> relu'd dup transpose into g_vd --------
// grid (MAXWL, 4 hc of 64), 128 thr. Warp = 8 tok x 64 h (2 h/lane).
// per kk: 1 LDS.64 (W) + 4 broadcast LDS.128 (x-dup) + 8 FFMA2,
// register double-buffered operands.
__global__ __launch_bounds__(128) void ffn1_kernel(
    const float* __restrict__ w1s, const float* __restrict__ b1s,
    const float* __restrict__ x)
{
    __shared__ __align__(16) float ws[32][68];   // [i 32][h 64 + 4]  8.7 KB
    __shared__ __align__(16) u64 xd[32][34];     // [k][tok] dup      8.7 KB
    __shared__ int tok[32];
    int bx = blockIdx.x;
    if (bx >= g_wl_n) return;
    int ent = g_wl[bx];
    int e = ent >> 16, c0 = ent & 0xffff;
    int hc = blockIdx.y;                         // 64-col tile
    int s = g_seg_start[e];
    int nt = min(CH, g_seg_cnt[e] - c0);
    int tid = threadIdx.x, w = tid >> 5, l = tid & 31;
    const float* wbase = w1s + (size_t)e * IW * H + hc * 64;

    int wr[4], wc[4];
#pragma unroll
    for (int q = 0; q < 4; q++) {
        int f4 = tid + 128 * q;                  // 512 float4s
        wr[q] = f4 >> 4; wc[q] = (f4 & 15) * 4;
    }
    int xk = tid & 31;
    int xtt[8];
#pragma unroll
    for (int q = 0; q < 8; q++) xtt[q] = (tid >> 5) + 4 * q;

    if (tid < 32) tok[tid] = (tid < nt) ? (g_perm_a[s + c0 + tid] >> 1) : -1;
    __syncthreads();
    int tki[8];
#pragma unroll
    for (int q = 0; q < 8; q++) tki[q] = tok[xtt[q]];

    // prologue prefetch: tile i0 = 0
    float4 pw[4]; float px[8];
#pragma unroll
    for (int q = 0; q < 4; q++)
        pw[q] = *(const float4*)(wbase + (size_t)wr[q] * H + wc[q]);
#pragma unroll
    for (int q = 0; q < 8; q++)
        px[q] = (tki[q] >= 0) ? x[tki[q] * IW + xk] : 0.f;

    u64 acc[8];
    float2 bv = *(const float2*)(b1s + e * H + hc * 64 + l * 2);
    u64 binit = pack2(bv.x, bv.y);
#pragma unroll
    for (int j = 0; j < 8; j++) acc[j] = binit;

    for (int i0 = 0; i0 < IW; i0 += 32) {
#pragma unroll
        for (int q = 0; q < 4; q++)
            *(float4*)&ws[wr[q]][wc[q]] = pw[q];
#pragma unroll
        for (int q = 0; q < 8; q++)
            xd[xk][xtt[q]] = pack2(px[q], px[q]);
        __syncthreads();

        if (i0 + 32 < IW) {
            const float* wb = wbase + (size_t)(i0 + 32) * H;
#pragma unroll
            for (int q = 0; q < 4; q++)
                pw[q] = *(const float4*)(wb + (size_t)wr[q] * H + wc[q]);
#pragma unroll
            for (int q = 0; q < 8; q++)
                px[q] = (tki[q] >= 0) ? x[tki[q] * IW + i0 + 32 + xk] : 0.f;
        }
        // register double-buffered smem operands
        u64 wv = *(u64*)&ws[0][l * 2];
        ulonglong2 xa = *(ulonglong2*)&xd[0][w * 8];
        ulonglong2 xb = *(ulonglong2*)&xd[0][w * 8 + 2];
        ulonglong2 xc = *(ulonglong2*)&xd[0][w * 8 + 4];
        ulonglong2 xe = *(ulonglong2*)&xd[0][w * 8 + 6];
#pragma unroll
        for (int kk = 0; kk < 32; kk++) {
            u64 wn; ulonglong2 xan, xbn, xcn, xen;
            if (kk < 31) {
                wn  = *(u64*)&ws[kk + 1][l * 2];
                xan = *(ulonglong2*)&xd[kk + 1][w * 8];
                xbn = *(ulonglong2*)&xd[kk + 1][w * 8 + 2];
                xcn = *(ulonglong2*)&xd[kk + 1][w * 8 + 4];
                xen = *(ulonglong2*)&xd[kk + 1][w * 8 + 6];
            }
            ffma2(acc[0], xa.x, wv); ffma2(acc[1], xa.y, wv);
            ffma2(acc[2], xb.x, wv); ffma2(acc[3], xb.y, wv);
            ffma2(acc[4], xc.x, wv); ffma2(acc[5], xc.y, wv);
            ffma2(acc[6], xe.x, wv); ffma2(acc[7], xe.y, wv);
            if (kk < 31) { wv = wn; xa = xan; xb = xbn; xc = xcn; xe = xen; }
        }
        __syncthreads();
    }

    // epilogue: relu + transposed dup write g_vd[h][perm]
    float r[8][2];
#pragma unroll
    for (int j = 0; j < 8; j++) {
        float2 f = unpack2(acc[j]);
        r[j][0] = fmaxf(f.x, 0.f); r[j][1] = fmaxf(f.y, 0.f);
    }
    int hbase = hc * 64 + l * 2;
    int pbase = s + c0 + w * 8;
    int rem = nt - w * 8;
    if (rem >= 8) {
#pragma unroll
        for (int hh = 0; hh < 2; hh++) {
            u64* dst = g_vd + (size_t)(hbase + hh) * XP + pbase;
            ulonglong2 v0, v1, v2, v3;
            v0.x = pack2(r[0][hh], r[0][hh]); v0.y = pack2(r[1][hh], r[1][hh]);
            v1.x = pack2(r[2][hh], r[2][hh]); v1.y = pack2(r[3][hh], r[3][hh]);
            v2.x = pack2(r[4][hh], r[4][hh]); v2.y = pack2(r[5][hh], r[5][hh]);
            v3.x = pack2(r[6][hh], r[6][hh]); v3.y = pack2(r[7][hh], r[7][hh]);
            *(ulonglong2*)(dst + 0) = v0;
            *(ulonglong2*)(dst + 2) = v1;
            *(ulonglong2*)(dst + 4) = v2;
            *(ulonglong2*)(dst + 6) = v3;
        }
    } else if (rem > 0) {
        for (int j = 0; j < rem; j++)
#pragma unroll
            for (int hh = 0; hh < 2; hh++)
                g_vd[(size_t)(hbase + hh) * XP + pbase + j] = pack2(r[j][hh], r[j][hh]);
    }
}

// ---------------- kernel 4: ffn2: out += score * (relu(V) @ W2 + b2) --------
// grid (MAXWL, 8 oc of 64), 128 thr. Warp = 8 tok x 64 o (2 o/lane).
// V-dup rows staged g_vd -> smem (coalesced), broadcast LDS in mainloop.
// Atomic epilogue: exactly 2 commutative adds per out element -> deterministic.
__global__ __launch_bounds__(128) void ffn2_kernel(
    const float* __restrict__ w2s, const float* __restrict__ b2s,
    float* __restrict__ out)
{
    __shared__ __align__(16) float ws2[32][68];  // 8.7 KB
    __shared__ __align__(16) u64 vd2[32][34];    // 8.7 KB
    int bx = blockIdx.x;
    if (bx >= g_wl_n) return;
    int ent = g_wl[bx];
    int e = ent >> 16, c0 = ent & 0xffff;
    int oc = blockIdx.y;                         // 64-col tile
    int s = g_seg_start[e];
    int nt = min(CH, g_seg_cnt[e] - c0);
    int tid = threadIdx.x, w = tid >> 5, l = tid & 31;
    const float* wbase = w2s + (size_t)e * H * OW + oc * 64;
    int pbase0 = s + c0;

    int wr[4], wc[4];
#pragma unroll
    for (int q = 0; q < 4; q++) {
        int f4 = tid + 128 * q;
        wr[q] = f4 >> 4; wc[q] = (f4 & 15) * 4;
    }
    int vhh[4], vcc[4];
#pragma unroll
    for (int q = 0; q < 4; q++) {
        int id = tid + 128 * q;                  // 512 ulonglong2
        vhh[q] = id >> 4; vcc[q] = (id & 15) * 2;
    }

    // prologue prefetch: tile h0 = 0
    float4 pw[4]; ulonglong2 pv[4];
#pragma unroll
    for (int q = 0; q < 4; q++)
        pw[q] = *(const float4*)(wbase + (size_t)wr[q] * OW + wc[q]);
#pragma unroll
    for (int q = 0; q < 4; q++)
        pv[q] = *(const ulonglong2*)(g_vd + (size_t)vhh[q] * XP + pbase0 + vcc[q]);

    u64 acc[8];
    float2 bv = *(const float2*)(b2s + e * OW + oc * 64 + l * 2);
    u64 binit = pack2(bv.x, bv.y);
#pragma unroll
    for (int j = 0; j < 8; j++) acc[j] = binit;

    for (int h0 = 0; h0 < H; h0 += 32) {
#pragma unroll
        for (int q = 0; q < 4; q++)
            *(float4*)&ws2[wr[q]][wc[q]] = pw[q];
#pragma unroll
        for (int q = 0; q < 4; q++)
            *(ulonglong2*)&vd2[vhh[q]][vcc[q]] = pv[q];
        __syncthreads();

        if (h0 + 32 < H) {
            const float* wb = wbase + (size_t)(h0 + 32) * OW;
#pragma unroll
            for (int q = 0; q < 4; q++)
                pw[q] = *(const float4*)(wb + (size_t)wr[q] * OW + wc[q]);
#pragma unroll
            for (int q = 0; q < 4; q++)
                pv[q] = *(const ulonglong2*)(g_vd +
                    (size_t)(h0 + 32 + vhh[q]) * XP + pbase0 + vcc[q]);
        }
        u64 wv = *(u64*)&ws2[0][l * 2];
        ulonglong2 va = *(ulonglong2*)&vd2[0][w * 8];
        ulonglong2 vb = *(ulonglong2*)&vd2[0][w * 8 + 2];
        ulonglong2 vc = *(ulonglong2*)&vd2[0][w * 8 + 4];
        ulonglong2 ve = *(ulonglong2*)&vd2[0][w * 8 + 6];
#pragma unroll
        for (int kk = 0; kk < 32; kk++) {
            u64 wn; ulonglong2 van, vbn, vcn, ven;
            if (kk < 31) {
                wn  = *(u64*)&ws2[kk + 1][l * 2];
                van = *(ulonglong2*)&vd2[kk + 1][w * 8];
                vbn = *(ulonglong2*)&vd2[kk + 1][w * 8 + 2];
                vcn = *(ulonglong2*)&vd2[kk + 1][w * 8 + 4];
                ven = *(ulonglong2*)&vd2[kk + 1][w * 8 + 6];
            }
            ffma2(acc[0], va.x, wv); ffma2(acc[1], va.y, wv);
            ffma2(acc[2], vb.x, wv); ffma2(acc[3], vb.y, wv);
            ffma2(acc[4], vc.x, wv); ffma2(acc[5], vc.y, wv);
            ffma2(acc[6], ve.x, wv); ffma2(acc[7], ve.y, wv);
            if (kk < 31) { wv = wn; va = van; vb = vbn; vc = vcn; ve = ven; }
        }
        __syncthreads();
    }

#pragma unroll
    for (int j = 0; j < 8; j++) {
        int t = w * 8 + j;
        if (t < nt) {
            int   a  = g_perm_a[s + c0 + t];
            float sc = g_perm_score[s + c0 + t];
            int   tk = a >> 1;
            float* dst = out + (size_t)tk * OW + oc * 64 + l * 2;
            float2 f = unpack2(acc[j]);
            atomicAdd(dst + 0, sc * f.x);
            atomicAdd(dst + 1, sc * f.y);
        }
    }
}

// ---------------- launcher ----------------
extern "C" void kernel_launch(void* const* d_in, const int* in_sizes, int n_in,
                              void* d_out, int out_size)
{
    const float* x     = (const float*)d_in[0];
    const float* noise = (const float*)d_in[1];
    const float* w1s   = (const float*)d_in[2];
    const float* b1s   = (const float*)d_in[3];
    const float* w2s   = (const float*)d_in[4];
    const float* b2s   = (const float*)d_in[5];
    const float* mixer = (const float*)d_in[6];
    const float* nctl  = (const float*)d_in[7];

    routing_kernel<<<128, 256>>>(x, noise, mixer, nctl, (float4*)d_out);
    group_kernel<<<1, 256>>>();
    ffn1_kernel<<<dim3(MAXWL, 4), 128>>>(w1s, b1s, x);
    ffn2_kernel<<<dim3(MAXWL, 8), 128>>>(w2s, b2s, (float*)d_out);
}

// round 17
// speedup vs baseline: 1.0558x; 1.0558x over previous
#include <cuda_runtime.h>

#define IW 512
#define H 256
#define OW 512
#define E 64
#define NA 2048
#define NAP 2560
#define XP 2560           // column stride of g_vd
#define CH 32             // token chunk per worklist entry
#define MAXWL 128

typedef unsigned long long u64;

// ---------------- device scratch (no allocs allowed) ----------------
__device__ __align__(16) u64   g_vd[(size_t)H * XP];   // 5.2 MB (relu v, relu v) dup [h][perm]
__device__ int   g_topk_idx[NA];
__device__ float g_topk_score[NA];
__device__ int   g_seg_start[E + 1];
__device__ int   g_seg_cnt[E];
__device__ int   g_perm_a[NAP];
__device__ float g_perm_score[NAP];
__device__ int   g_wl[MAXWL];      // (expert<<16) | chunk_start
__device__ int   g_wl_n;

// ---------------- packed f32x2 helpers (sm_103a) ----------------
__device__ __forceinline__ u64 pack2(float a, float b) {
    u64 r; unsigned ai = __float_as_uint(a), bi = __float_as_uint(b);
    asm("mov.b64 %0, {%1, %2};" : "=l"(r) : "r"(ai), "r"(bi));
    return r;
}
__device__ __forceinline__ void ffma2(u64 &d, u64 a, u64 b) {
    asm("fma.rn.f32x2 %0, %1, %2, %0;" : "+l"(d) : "l"(a), "l"(b));
}
__device__ __forceinline__ float2 unpack2(u64 v) {
    unsigned lo, hi;
    asm("mov.b64 {%0, %1}, %2;" : "=r"(lo), "=r"(hi) : "l"(v));
    float2 f; f.x = __uint_as_float(lo); f.y = __uint_as_float(hi);
    return f;
}

// ---------------- kernel 1: routing (+ fused d_out zeroing) ----------------
__global__ __launch_bounds__(256) void routing_kernel(
    const float* __restrict__ x, const float* __restrict__ noise,
    const float* __restrict__ mixer, const float* __restrict__ nctl,
    float4* __restrict__ out)
{
    __shared__ __align__(16) u64 mns[32][64];
    __shared__ __align__(16) u64 xs2[8][32];
    __shared__ float hs[8][64];
    int tid = threadIdx.x;
    int t0 = blockIdx.x * 8;
    int ee = tid & 63, tg = tid >> 6;

    {   // fused zero of d_out: 131072 float4 over 32768 threads
        int base = blockIdx.x * 256 + tid;
        float4 z = make_float4(0.f, 0.f, 0.f, 0.f);
#pragma unroll
        for (int q = 0; q < 4; q++) out[base + q * 32768] = z;
    }

    u64 acc2[2] = {0ull, 0ull};

    for (int i0 = 0; i0 < IW; i0 += 32) {
#pragma unroll
        for (int q = 0; q < 8; q++) {
            int id = tid + 256 * q; int ii = id >> 6, e2 = id & 63;
            mns[ii][e2] = pack2(mixer[(i0 + ii) * E + e2], nctl[(i0 + ii) * E + e2]);
        }
        {
            int tt = tid >> 5, ii = tid & 31;
            if (tt < 8) {
                float v = x[(t0 + tt) * IW + i0 + ii];
                xs2[tt][ii] = pack2(v, v);
            }
        }
        __syncthreads();
#pragma unroll 8
        for (int ii = 0; ii < 32; ii++) {
            u64 mn = mns[ii][ee];
            ffma2(acc2[0], xs2[tg * 2 + 0][ii], mn);
            ffma2(acc2[1], xs2[tg * 2 + 1][ii], mn);
        }
        __syncthreads();
    }

#pragma unroll
    for (int j = 0; j < 2; j++) {
        int t = tg * 2 + j;
        float2 a = unpack2(acc2[j]);
        float z = a.y;
        float sp = (z > 20.f) ? z : log1pf(expf(z));
        hs[t][ee] = a.x + noise[(t0 + t) * E + ee] * sp;
    }
    __syncthreads();

    if (tid < 8) {
        int t = tid;
        float v0 = -1e30f, v1 = -1e30f; int i0 = -1, i1 = -1;
        for (int ec = 0; ec < 64; ec++) {
            float v = hs[t][ec];
            if (v > v0)      { v1 = v0; i1 = i0; v0 = v; i0 = ec; }
            else if (v > v1) { v1 = v; i1 = ec; }
        }
        float e1 = expf(v1 - v0);
        float s0 = 1.f / (1.f + e1);
        float s1 = e1 * s0;
        g_topk_idx[(t0 + t) * 2 + 0] = i0;
        g_topk_idx[(t0 + t) * 2 + 1] = i1;
        g_topk_score[(t0 + t) * 2 + 0] = s0;
        g_topk_score[(t0 + t) * 2 + 1] = s1;
    }
}

// ---------------- kernel 2: group + deterministic worklist ----------------
__global__ __launch_bounds__(256) void group_kernel()
{
    __shared__ int cnt4[4][E];
    __shared__ int st[E + 1];
    __shared__ int cur[E];
    __shared__ int wo[E];
    int tid = threadIdx.x;
    int grp = tid >> 6;
    if (tid < E) { cnt4[0][tid] = 0; cnt4[1][tid] = 0; cnt4[2][tid] = 0; cnt4[3][tid] = 0; }
    __syncthreads();
    for (int a = tid; a < NA; a += 256) atomicAdd(&cnt4[grp][g_topk_idx[a]], 1);
    __syncthreads();
    if (tid < E) cnt4[0][tid] += cnt4[1][tid] + cnt4[2][tid] + cnt4[3][tid];
    __syncthreads();
    if (tid == 0) {
        int run = 0, wrun = 0;
        for (int e2 = 0; e2 < E; e2++) {
            st[e2] = run;
            run = (run + cnt4[0][e2] + 7) & ~7;  // 8-aligned segment starts
            wo[e2] = wrun;
            wrun += (cnt4[0][e2] + CH - 1) / CH;
        }
        st[E] = run;
        g_wl_n = wrun;
    }
    __syncthreads();
    if (tid < E) { cur[tid] = st[tid]; g_seg_cnt[tid] = cnt4[0][tid]; }
    if (tid <= E) g_seg_start[tid] = st[tid];
    __syncthreads();
    for (int a = tid; a < NA; a += 256) {
        int e2 = g_topk_idx[a];
        int pos = atomicAdd(&cur[e2], 1);
        g_perm_a[pos] = a;
        g_perm_score[pos] = g_topk_score[a];
    }
    __syncthreads();
    if (tid < E) {
        for (int p = st[tid] + cnt4[0][tid]; p < st[tid + 1]; p++) {
            g_perm_a[p] = 0; g_perm_score[p] = 0.f;
        }
        for (int c = 0; c * CH < cnt4[0][tid]; c++)
            g_wl[wo[tid] + c] = (tid << 16) | (c * CH);
    }
    for (int p = st[E] + tid; p < NAP; p += 256) {
        g_perm_a[p] = 0; g_perm_score[p] = 0.f;
    }
}

// ---------------- kernel 3: ffn1 -> relu'd dup transpose into g_vd --------
// grid (MAXWL, 4 hc of 64), 128 thr = 4 warps = (2 tok-halves x 2 col-halves).
// Warp = 16 tok x 32 h; thread = 4 tok x 4 h.
// per kk per thread: 2 LDS.128 (x-dup, multicast) + 1 LDS.128 (w) + 8 FFMA2.
__global__ __launch_bounds__(128) void ffn1_kernel(
    const float* __restrict__ w1s, const float* __restrict__ b1s,
    const float* __restrict__ x)
{
    __shared__ __align__(16) float ws[32][68];   // [i 32][h 64 + 4]  8.7 KB
    __shared__ __align__(16) u64 xd[32][34];     // [i][tok dup]      8.7 KB
    __shared__ int tok[32];
    int bx = blockIdx.x;
    if (bx >= g_wl_n) return;
    int ent = g_wl[bx];
    int e = ent >> 16, c0 = ent & 0xffff;
    int hc = blockIdx.y;                         // 64-col tile
    int s = g_seg_start[e];
    int nt = min(CH, g_seg_cnt[e] - c0);
    int tid = threadIdx.x, w = tid >> 5, l = tid & 31;
    int wr = w >> 1, wg = w & 1;                 // token half / col half
    int tr = l >> 3, tc = l & 7;                 // thread tile coords
    int tbase = wr * 16 + tr * 4;                // first of 4 tokens
    int cbase = wg * 32 + tc * 4;                // first of 4 cols
    const float* wbase = w1s + (size_t)e * IW * H + hc * 64;

    int wrr[4], wcc[4];
#pragma unroll
    for (int q = 0; q < 4; q++) {
        int f4 = tid + 128 * q;                  // 512 float4s
        wrr[q] = f4 >> 4; wcc[q] = (f4 & 15) * 4;
    }
    int xk = tid & 31;
    int xtt[8];
#pragma unroll
    for (int q = 0; q < 8; q++) xtt[q] = (tid >> 5) + 4 * q;

    if (tid < 32) tok[tid] = (tid < nt) ? (g_perm_a[s + c0 + tid] >> 1) : -1;
    __syncthreads();
    int tki[8];
#pragma unroll
    for (int q = 0; q < 8; q++) tki[q] = tok[xtt[q]];

    // prologue prefetch: tile i0 = 0
    float4 pw[4]; float px[8];
#pragma unroll
    for (int q = 0; q < 4; q++)
        pw[q] = *(const float4*)(wbase + (size_t)wrr[q] * H + wcc[q]);
#pragma unroll
    for (int q = 0; q < 8; q++)
        px[q] = (tki[q] >= 0) ? x[tki[q] * IW + xk] : 0.f;

    u64 acc[4][2];
    float4 bv = *(const float4*)(b1s + e * H + hc * 64 + cbase);
#pragma unroll
    for (int j = 0; j < 4; j++) {
        acc[j][0] = pack2(bv.x, bv.y);
        acc[j][1] = pack2(bv.z, bv.w);
    }

    for (int i0 = 0; i0 < IW; i0 += 32) {
#pragma unroll
        for (int q = 0; q < 4; q++)
            *(float4*)&ws[wrr[q]][wcc[q]] = pw[q];
#pragma unroll
        for (int q = 0; q < 8; q++)
            xd[xk][xtt[q]] = pack2(px[q], px[q]);
        __syncthreads();

        if (i0 + 32 < IW) {
            const float* wb = wbase + (size_t)(i0 + 32) * H;
#pragma unroll
            for (int q = 0; q < 4; q++)
                pw[q] = *(const float4*)(wb + (size_t)wrr[q] * H + wcc[q]);
#pragma unroll
            for (int q = 0; q < 8; q++)
                px[q] = (tki[q] >= 0) ? x[tki[q] * IW + i0 + 32 + xk] : 0.f;
        }
#pragma unroll 8
        for (int kk = 0; kk < 32; kk++) {
            ulonglong2 wl2 = *(ulonglong2*)&ws[kk][cbase];
            ulonglong2 a01 = *(ulonglong2*)&xd[kk][tbase];
            ulonglong2 a23 = *(ulonglong2*)&xd[kk][tbase + 2];
            ffma2(acc[0][0], a01.x, wl2.x); ffma2(acc[0][1], a01.x, wl2.y);
            ffma2(acc[1][0], a01.y, wl2.x); ffma2(acc[1][1], a01.y, wl2.y);
            ffma2(acc[2][0], a23.x, wl2.x); ffma2(acc[2][1], a23.x, wl2.y);
            ffma2(acc[3][0], a23.y, wl2.x); ffma2(acc[3][1], a23.y, wl2.y);
        }
        __syncthreads();
    }

    // epilogue: relu + transposed dup write g_vd[h][perm]
    float r[4][4];
#pragma unroll
    for (int j = 0; j < 4; j++) {
        float2 f0 = unpack2(acc[j][0]), f1 = unpack2(acc[j][1]);
        r[j][0] = fmaxf(f0.x, 0.f); r[j][1] = fmaxf(f0.y, 0.f);
        r[j][2] = fmaxf(f1.x, 0.f); r[j][3] = fmaxf(f1.y, 0.f);
    }
    int hbase = hc * 64 + cbase;
    int pbase = s + c0 + tbase;
    int rem = nt - tbase;
    if (rem >= 4) {
#pragma unroll
        for (int hh = 0; hh < 4; hh++) {
            u64* dst = g_vd + (size_t)(hbase + hh) * XP + pbase;
            ulonglong2 v0, v1;
            v0.x = pack2(r[0][hh], r[0][hh]); v0.y = pack2(r[1][hh], r[1][hh]);
            v1.x = pack2(r[2][hh], r[2][hh]); v1.y = pack2(r[3][hh], r[3][hh]);
            *(ulonglong2*)(dst + 0) = v0;
            *(ulonglong2*)(dst + 2) = v1;
        }
    } else if (rem > 0) {
        for (int j = 0; j < rem; j++)
#pragma unroll
            for (int hh = 0; hh < 4; hh++)
                g_vd[(size_t)(hbase + hh) * XP + pbase + j] = pack2(r[j][hh], r[j][hh]);
    }
}

// ---------------- kernel 4: ffn2: out += score * (relu(V) @ W2 + b2) --------
// grid (MAXWL, 8 oc of 64), 128 thr. Warp = 16 tok x 32 o; thread = 4 tok x 4 o.
// V-dup rows staged g_vd -> smem (coalesced copy), lane-indexed LDS in mainloop.
// Atomic epilogue: exactly 2 commutative adds per out element -> deterministic.
__global__ __launch_bounds__(128) void ffn2_kernel(
    const float* __restrict__ w2s, const float* __restrict__ b2s,
    float* __restrict__ out)
{
    __shared__ __align__(16) float ws2[32][68];  // 8.7 KB
    __shared__ __align__(16) u64 vd2[32][34];    // 8.7 KB
    int bx = blockIdx.x;
    if (bx >= g_wl_n) return;
    int ent = g_wl[bx];
    int e = ent >> 16, c0 = ent & 0xffff;
    int oc = blockIdx.y;                         // 64-col tile
    int s = g_seg_start[e];
    int nt = min(CH, g_seg_cnt[e] - c0);
    int tid = threadIdx.x, w = tid >> 5, l = tid & 31;
    int wr = w >> 1, wg = w & 1;
    int tr = l >> 3, tc = l & 7;
    int tbase = wr * 16 + tr * 4;
    int cbase = wg * 32 + tc * 4;
    const float* wbase = w2s + (size_t)e * H * OW + oc * 64;
    int pbase0 = s + c0;

    int wrr[4], wcc[4];
#pragma unroll
    for (int q = 0; q < 4; q++) {
        int f4 = tid + 128 * q;
        wrr[q] = f4 >> 4; wcc[q] = (f4 & 15) * 4;
    }
    int vhh[4], vcc[4];
#pragma unroll
    for (int q = 0; q < 4; q++) {
        int id = tid + 128 * q;                  // 512 ulonglong2
        vhh[q] = id >> 4; vcc[q] = (id & 15) * 2;
    }

    // prologue prefetch: tile h0 = 0
    float4 pw[4]; ulonglong2 pv[4];
#pragma unroll
    for (int q = 0; q < 4; q++)
        pw[q] = *(const float4*)(wbase + (size_t)wrr[q] * OW + wcc[q]);
#pragma unroll
    for (int q = 0; q < 4; q++)
        pv[q] = *(const ulonglong2*)(g_vd + (size_t)vhh[q] * XP + pbase0 + vcc[q]);

    u64 acc[4][2];
    float4 bv = *(const float4*)(b2s + e * OW + oc * 64 + cbase);
#pragma unroll
    for (int j = 0; j < 4; j++) {
        acc[j][0] = pack2(bv.x, bv.y);
        acc[j][1] = pack2(bv.z, bv.w);
    }

    for (int h0 = 0; h0 < H; h0 += 32) {
#pragma unroll
        for (int q = 0; q < 4; q++)
            *(float4*)&ws2[wrr[q]][wcc[q]] = pw[q];
#pragma unroll
        for (int q = 0; q < 4; q++)
            *(ulonglong2*)&vd2[vhh[q]][vcc[q]] = pv[q];
        __syncthreads();

        if (h0 + 32 < H) {
            const float* wb = wbase + (size_t)(h0 + 32) * OW;
#pragma unroll
            for (int q = 0; q < 4; q++)
                pw[q] = *(const float4*)(wb + (size_t)wrr[q] * OW + wcc[q]);
#pragma unroll
            for (int q = 0; q < 4; q++)
                pv[q] = *(const ulonglong2*)(g_vd +
                    (size_t)(h0 + 32 + vhh[q]) * XP + pbase0 + vcc[q]);
        }
#pragma unroll 8
        for (int kk = 0; kk < 32; kk++) {
            ulonglong2 wl2 = *(ulonglong2*)&ws2[kk][cbase];
            ulonglong2 a01 = *(ulonglong2*)&vd2[kk][tbase];
            ulonglong2 a23 = *(ulonglong2*)&vd2[kk][tbase + 2];
            ffma2(acc[0][0], a01.x, wl2.x); ffma2(acc[0][1], a01.x, wl2.y);
            ffma2(acc[1][0], a01.y, wl2.x); ffma2(acc[1][1], a01.y, wl2.y);
            ffma2(acc[2][0], a23.x, wl2.x); ffma2(acc[2][1], a23.x, wl2.y);
            ffma2(acc[3][0], a23.y, wl2.x); ffma2(acc[3][1], a23.y, wl2.y);
        }
        __syncthreads();
    }

#pragma unroll
    for (int j = 0; j < 4; j++) {
        int t = tbase + j;
        if (t < nt) {
            int   a  = g_perm_a[s + c0 + t];
            float sc = g_perm_score[s + c0 + t];
            int   tk = a >> 1;
            float* dst = out + (size_t)tk * OW + oc * 64 + cbase;
            float2 f0 = unpack2(acc[j][0]), f1 = unpack2(acc[j][1]);
            atomicAdd(dst + 0, sc * f0.x);
            atomicAdd(dst + 1, sc * f0.y);
            atomicAdd(dst + 2, sc * f1.x);
            atomicAdd(dst + 3, sc * f1.y);
        }
    }
}

// ---------------- launcher ----------------
extern "C" void kernel_launch(void* const* d_in, const int* in_sizes, int n_in,
                              void* d_out, int out_size)
{
    const float* x     = (const float*)d_in[0];
    const float* noise = (const float*)d_in[1];
    const float* w1s   = (const float*)d_in[2];
    const float* b1s   = (const float*)d_in[3];
    const float* w2s   = (const float*)d_in[4];
    const float* b2s   = (const float*)d_in[5];
    const float* mixer = (const float*)d_in[6];
    const float* nctl  = (const float*)d_in[7];

    routing_kernel<<<128, 256>>>(x, noise, mixer, nctl, (float4*)d_out);
    group_kernel<<<1, 256>>>();
    ffn1_kernel<<<dim3(MAXWL, 4), 128>>>(w1s, b1s, x);
    ffn2_kernel<<<dim3(MAXWL, 8), 128>>>(w2s, b2s, (float*)d_out);
}